// round 1
// baseline (speedup 1.0000x reference)
#include <cuda_runtime.h>
#include <math.h>

#define Nn 2
#define Hh 8
#define Ss 1024
#define DHh 64
#define Dd 512
#define Pp 2047   // 2S-1

// Scratch (device globals: no allocations allowed)
__device__ float g_ENC[Pp * Dd];          // positional encodings (2047 x 512) ~4.2MB
__device__ float g_R[Hh * Pp * DHh];      // r reshaped [h][p][d] ~4.2MB

// ---------------------------------------------------------------------------
// Kernel 1: positional encodings. One block per p, 256 threads (one per freq).
// ---------------------------------------------------------------------------
__global__ void enc_kernel() {
    int p = blockIdx.x;
    int i = threadIdx.x;                      // 0..255
    float pos = (float)(Ss - 1 - p);          // S-1 .. -(S-1)
    float inv = expf(-(2.0f * (float)i) * (logf(10000.0f) / (float)Dd));
    float s, c;
    sincosf(pos * inv, &s, &c);
    g_ENC[p * Dd + 2 * i]     = s;
    g_ENC[p * Dd + 2 * i + 1] = c;
}

// ---------------------------------------------------------------------------
// Kernel 2: R[h][p][d] = sum_j ENC[p][j] * W[(h*64+d)][j]
// Tiled SGEMM: BM=64 (p), BN=64 (c), BK=16. grid (32, 8), 256 threads.
// ---------------------------------------------------------------------------
__global__ void __launch_bounds__(256) rproj_kernel(const float* __restrict__ W) {
    __shared__ float As[16][68];   // As[kk][pp]  (ENC tile, transposed)
    __shared__ float Bsm[16][68];  // Bsm[kk][cc] (W tile, transposed)

    int p0 = blockIdx.x * 64;
    int c0 = blockIdx.y * 64;     // head = blockIdx.y
    int tid = threadIdx.x;
    int tx = tid & 15, ty = tid >> 4;

    float acc[4][4] = {};

    int jj = tid & 15;     // 0..15 (K within tile)
    int rr = tid >> 4;     // 0..15

    for (int j0 = 0; j0 < Dd; j0 += 16) {
#pragma unroll
        for (int r = 0; r < 4; r++) {
            int prow = rr + r * 16;
            float v = 0.0f;
            if (p0 + prow < Pp) v = g_ENC[(p0 + prow) * Dd + j0 + jj];
            As[jj][prow] = v;
            int cc = rr + r * 16;
            Bsm[jj][cc] = W[(c0 + cc) * Dd + j0 + jj];
        }
        __syncthreads();
#pragma unroll
        for (int kk = 0; kk < 16; kk++) {
            float4 a = *(const float4*)&As[kk][ty * 4];
            float4 b = *(const float4*)&Bsm[kk][tx * 4];
            float av[4] = {a.x, a.y, a.z, a.w};
            float bv[4] = {b.x, b.y, b.z, b.w};
#pragma unroll
            for (int ia = 0; ia < 4; ia++)
#pragma unroll
                for (int ib = 0; ib < 4; ib++)
                    acc[ia][ib] += av[ia] * bv[ib];
        }
        __syncthreads();
    }
#pragma unroll
    for (int ia = 0; ia < 4; ia++) {
        int p = p0 + ty * 4 + ia;
        if (p >= Pp) continue;
#pragma unroll
        for (int ib = 0; ib < 4; ib++) {
            int d = tx * 4 + ib;  // c & 63 since c0 is head*64
            g_R[blockIdx.y * (Pp * DHh) + p * DHh + d] = acc[ia][ib];
        }
    }
}

// ---------------------------------------------------------------------------
// Kernel 3: fused causal flash attention with relative-position scores.
// grid = (16 qtiles [reversed for load balance], 16 heads), 256 threads.
// score(i,j) = (qu[i].k[j] + qv[i].r[S-1-i+j]) * dh^-0.5, causal.
// BD computed as dense 64x128 GEMM over the r-band, gathered diagonally.
// ---------------------------------------------------------------------------
#define SM_QUT 0
#define SM_QVT (SM_QUT + 64 * 68)
#define SM_KST (SM_QVT + 64 * 68)
#define SM_VS  (SM_KST + 64 * 68)
#define SM_PS  (SM_VS  + 64 * 68)
#define SM_RST (SM_PS  + 64 * 68)   // 64 x 132
#define SM_BS  (SM_RST + 64 * 132)  // 64 x 132
#define SM_TOTAL (SM_BS + 64 * 132) // floats

__global__ void __launch_bounds__(256) attn_kernel(
    const float* __restrict__ seqs, const float* __restrict__ keys,
    const float* __restrict__ values, const float* __restrict__ u_bias,
    const float* __restrict__ v_bias, float* __restrict__ out)
{
    extern __shared__ float sm[];
    float* QuT = sm + SM_QUT;   // [d][i]   64x68
    float* QvT = sm + SM_QVT;   // [d][i]
    float* KsT = sm + SM_KST;   // [d][kj]
    float* Vs  = sm + SM_VS;    // [kj][d]
    float* Ps  = sm + SM_PS;    // [qi][kj]
    float* RsT = sm + SM_RST;   // [d][o]   64x132
    float* Bs  = sm + SM_BS;    // [qi][o]  64x132

    int qt = 15 - blockIdx.x;            // big blocks first
    int head = blockIdx.y;
    int n = head >> 3, h = head & 7;
    int i0 = qt * 64;
    int tid = threadIdx.x;
    int tx = tid & 15, ty = tid >> 4;

    const float* sq = seqs   + ((size_t)(n * Hh + h) * Ss) * DHh;
    const float* kq = keys   + ((size_t)(n * Hh + h) * Ss) * DHh;
    const float* vq = values + ((size_t)(n * Hh + h) * Ss) * DHh;
    const float* Rh = g_R + (size_t)h * (Pp * DHh);

    // Load Qu / Qv (transposed) once.
    {
        int d = tid & 63, i4 = tid >> 6;
        float ub = u_bias[h * DHh + d];
        float vb = v_bias[h * DHh + d];
#pragma unroll
        for (int r = 0; r < 16; r++) {
            int i = i4 + r * 4;
            float s = sq[(i0 + i) * DHh + d];
            QuT[d * 68 + i] = s + ub;
            QvT[d * 68 + i] = s + vb;
        }
    }

    float m[4], l[4], Oacc[4][4];
#pragma unroll
    for (int a = 0; a < 4; a++) {
        m[a] = -INFINITY; l[a] = 0.0f;
#pragma unroll
        for (int b = 0; b < 4; b++) Oacc[a][b] = 0.0f;
    }
    const float scale = 0.125f;  // 64^-0.5

    for (int kt = 0; kt <= qt; kt++) {
        int j0 = kt * 64;
        int pbase = (Ss - 1) - i0 + j0 - 63;   // always in [0, Pp-128]

        __syncthreads();  // previous iteration fully consumed
        {
            int d = tid & 63, r4 = tid >> 6;
#pragma unroll
            for (int r = 0; r < 16; r++) {
                int kj = r4 + r * 4;
                KsT[d * 68 + kj] = kq[(j0 + kj) * DHh + d];
                Vs[kj * 68 + d]  = vq[(j0 + kj) * DHh + d];
            }
#pragma unroll
            for (int r = 0; r < 32; r++) {
                int o = r4 + r * 4;
                RsT[d * 132 + o] = Rh[(pbase + o) * DHh + d];
            }
        }
        __syncthreads();

        // BD = Qv (64x64) @ R_band^T (64x128): per-thread 4 rows x (4+4) cols
        float bdA[4][4] = {}, bdB[4][4] = {};
#pragma unroll 16
        for (int kk = 0; kk < 64; kk++) {
            float4 q  = *(const float4*)&QvT[kk * 68 + ty * 4];
            float4 rA = *(const float4*)&RsT[kk * 132 + tx * 4];
            float4 rB = *(const float4*)&RsT[kk * 132 + 64 + tx * 4];
            float qv[4] = {q.x, q.y, q.z, q.w};
            float ra[4] = {rA.x, rA.y, rA.z, rA.w};
            float rb[4] = {rB.x, rB.y, rB.z, rB.w};
#pragma unroll
            for (int a = 0; a < 4; a++) {
#pragma unroll
                for (int b = 0; b < 4; b++) {
                    bdA[a][b] += qv[a] * ra[b];
                    bdB[a][b] += qv[a] * rb[b];
                }
            }
        }
#pragma unroll
        for (int a = 0; a < 4; a++)
#pragma unroll
            for (int b = 0; b < 4; b++) {
                Bs[(ty * 4 + a) * 132 + tx * 4 + b]      = bdA[a][b];
                Bs[(ty * 4 + a) * 132 + 64 + tx * 4 + b] = bdB[a][b];
            }

        // AC = Qu (64x64) @ K^T (64x64)
        float ac[4][4] = {};
#pragma unroll 16
        for (int kk = 0; kk < 64; kk++) {
            float4 q = *(const float4*)&QuT[kk * 68 + ty * 4];
            float4 k = *(const float4*)&KsT[kk * 68 + tx * 4];
            float qv[4] = {q.x, q.y, q.z, q.w};
            float kv[4] = {k.x, k.y, k.z, k.w};
#pragma unroll
            for (int a = 0; a < 4; a++)
#pragma unroll
                for (int b = 0; b < 4; b++)
                    ac[a][b] += qv[a] * kv[b];
        }
        __syncthreads();  // Bs visible

        // Scores + online softmax (rows owned by the 16 lanes sharing ty)
        bool diag = (kt == qt);
#pragma unroll
        for (int a = 0; a < 4; a++) {
            int qi = ty * 4 + a;
            float sreg[4];
            float mx = -INFINITY;
#pragma unroll
            for (int b = 0; b < 4; b++) {
                int kj = tx * 4 + b;
                float s = (ac[a][b] + Bs[qi * 132 + (kj - qi + 63)]) * scale;
                if (diag && kj > qi) s = -INFINITY;
                sreg[b] = s;
                mx = fmaxf(mx, s);
            }
#pragma unroll
            for (int o = 8; o > 0; o >>= 1)
                mx = fmaxf(mx, __shfl_xor_sync(0xffffffffu, mx, o, 16));
            float mnew = fmaxf(m[a], mx);
            float corr = __expf(m[a] - mnew);
            float sum = 0.0f;
#pragma unroll
            for (int b = 0; b < 4; b++) {
                float e = __expf(sreg[b] - mnew);
                Ps[qi * 68 + tx * 4 + b] = e;
                sum += e;
            }
#pragma unroll
            for (int o = 8; o > 0; o >>= 1)
                sum += __shfl_xor_sync(0xffffffffu, sum, o, 16);
            l[a] = l[a] * corr + sum;
            m[a] = mnew;
#pragma unroll
            for (int b = 0; b < 4; b++) Oacc[a][b] *= corr;
        }
        __syncthreads();  // Ps visible

        // O += P (64x64) @ V (64x64); thread owns rows ty*4.., dims tx*4..
#pragma unroll 16
        for (int kk = 0; kk < 64; kk++) {
            float4 v = *(const float4*)&Vs[kk * 68 + tx * 4];
            float vv[4] = {v.x, v.y, v.z, v.w};
#pragma unroll
            for (int a = 0; a < 4; a++) {
                float p = Ps[(ty * 4 + a) * 68 + kk];
#pragma unroll
                for (int b = 0; b < 4; b++) Oacc[a][b] += p * vv[b];
            }
        }
    }

    // Epilogue
#pragma unroll
    for (int a = 0; a < 4; a++) {
        int qi = ty * 4 + a;
        float inv = 1.0f / l[a];
        float4 o4;
        o4.x = Oacc[a][0] * inv; o4.y = Oacc[a][1] * inv;
        o4.z = Oacc[a][2] * inv; o4.w = Oacc[a][3] * inv;
        *(float4*)&out[((size_t)(n * Hh + h) * Ss + i0 + qi) * DHh + tx * 4] = o4;
    }
}

// ---------------------------------------------------------------------------
extern "C" void kernel_launch(void* const* d_in, const int* in_sizes, int n_in,
                              void* d_out, int out_size) {
    const float* seqs   = (const float*)d_in[0];
    const float* keys   = (const float*)d_in[1];
    const float* values = (const float*)d_in[2];
    const float* u_bias = (const float*)d_in[3];
    const float* v_bias = (const float*)d_in[4];
    const float* rproj  = (const float*)d_in[5];
    // d_in[6] (attn_mask) is log(tril) == causal; applied analytically.
    (void)in_sizes; (void)n_in; (void)out_size;

    const int smem_bytes = SM_TOTAL * sizeof(float);  // ~151 KB
    cudaFuncSetAttribute(attn_kernel, cudaFuncAttributeMaxDynamicSharedMemorySize,
                         smem_bytes);

    enc_kernel<<<Pp, 256>>>();
    rproj_kernel<<<dim3(32, 8), 256>>>(rproj);
    attn_kernel<<<dim3(16, 16), 256, smem_bytes>>>(seqs, keys, values,
                                                   u_bias, v_bias,
                                                   (float*)d_out);
}

// round 2
// speedup vs baseline: 2.4659x; 2.4659x over previous
#include <cuda_runtime.h>
#include <math.h>

#define Nn 2
#define Hh 8
#define Ss 1024
#define DHh 64
#define Dd 512
#define Pp 2047   // 2S-1

// Scratch (device globals: no allocations allowed)
__device__ float g_ENC[Pp * Dd];          // positional encodings (2047 x 512)
__device__ float g_R[Hh * Pp * DHh];      // r reshaped [h][p][d]

// ---------------------------------------------------------------------------
// Kernel 1: positional encodings.
// ---------------------------------------------------------------------------
__global__ void enc_kernel() {
    int p = blockIdx.x;
    int i = threadIdx.x;                      // 0..255
    float pos = (float)(Ss - 1 - p);
    float inv = expf(-(2.0f * (float)i) * (logf(10000.0f) / (float)Dd));
    float s, c;
    sincosf(pos * inv, &s, &c);
    g_ENC[p * Dd + 2 * i]     = s;
    g_ENC[p * Dd + 2 * i + 1] = c;
}

// ---------------------------------------------------------------------------
// Kernel 2: R[h][p][d] = sum_j ENC[p][j] * W[(h*64+d)][j]  (SIMT SGEMM)
// ---------------------------------------------------------------------------
__global__ void __launch_bounds__(256) rproj_kernel(const float* __restrict__ W) {
    __shared__ float As[16][68];
    __shared__ float Bsm[16][68];

    int p0 = blockIdx.x * 64;
    int c0 = blockIdx.y * 64;
    int tid = threadIdx.x;
    int tx = tid & 15, ty = tid >> 4;

    float acc[4][4] = {};
    int jj = tid & 15;
    int rr = tid >> 4;

    for (int j0 = 0; j0 < Dd; j0 += 16) {
#pragma unroll
        for (int r = 0; r < 4; r++) {
            int prow = rr + r * 16;
            float v = 0.0f;
            if (p0 + prow < Pp) v = g_ENC[(p0 + prow) * Dd + j0 + jj];
            As[jj][prow] = v;
            int cc = rr + r * 16;
            Bsm[jj][cc] = W[(c0 + cc) * Dd + j0 + jj];
        }
        __syncthreads();
#pragma unroll
        for (int kk = 0; kk < 16; kk++) {
            float4 a = *(const float4*)&As[kk][ty * 4];
            float4 b = *(const float4*)&Bsm[kk][tx * 4];
            float av[4] = {a.x, a.y, a.z, a.w};
            float bv[4] = {b.x, b.y, b.z, b.w};
#pragma unroll
            for (int ia = 0; ia < 4; ia++)
#pragma unroll
                for (int ib = 0; ib < 4; ib++)
                    acc[ia][ib] += av[ia] * bv[ib];
        }
        __syncthreads();
    }
#pragma unroll
    for (int ia = 0; ia < 4; ia++) {
        int p = p0 + ty * 4 + ia;
        if (p >= Pp) continue;
#pragma unroll
        for (int ib = 0; ib < 4; ib++)
            g_R[blockIdx.y * (Pp * DHh) + p * DHh + tx * 4 + ib] = acc[ia][ib];
    }
}

// ---------------------------------------------------------------------------
// Kernel 3: fused causal flash attention, tf32 tensor cores (mma.sync m16n8k8)
// grid (8, 16): block bx handles qtiles {15-bx, bx} (17 k-tiles total, balanced)
// ---------------------------------------------------------------------------
#define SQU 0            // Qu [64][68]
#define SQV (SQU + 64*68)
#define SKS (SQV + 64*68)   // Ks [kj][d] [64][68]
#define SVS (SKS + 64*68)   // Vs [kj][d] [64][72]
#define SRS (SVS + 64*72)   // Rs [o][d]  [128][68]
#define SSC (SRS + 128*68)  // scores / P [64][68]
#define SBS (SSC + 64*68)   // BD dense   [64][132]
#define SMM (SBS + 64*132)  // m [64]
#define SLL (SMM + 64)      // l [64]
#define SCR (SLL + 64)      // corr [64]
#define STOT (SCR + 64)

__device__ __forceinline__ unsigned f2tf(float x) {
    unsigned r;
    asm("cvt.rna.tf32.f32 %0, %1;" : "=r"(r) : "f"(x));
    return r;
}
__device__ __forceinline__ void mma_tf32(float c[4], unsigned a0, unsigned a1,
                                         unsigned a2, unsigned a3,
                                         unsigned b0, unsigned b1) {
    asm volatile(
        "mma.sync.aligned.m16n8k8.row.col.f32.tf32.tf32.f32 "
        "{%0,%1,%2,%3},{%4,%5,%6,%7},{%8,%9},{%0,%1,%2,%3};"
        : "+f"(c[0]), "+f"(c[1]), "+f"(c[2]), "+f"(c[3])
        : "r"(a0), "r"(a1), "r"(a2), "r"(a3), "r"(b0), "r"(b1));
}
__device__ __forceinline__ unsigned ldb(const float* p) {
    return __float_as_uint(*p);
}

__global__ void __launch_bounds__(256) attn_kernel(
    const float* __restrict__ seqs, const float* __restrict__ keys,
    const float* __restrict__ values, const float* __restrict__ u_bias,
    const float* __restrict__ v_bias, float* __restrict__ out)
{
    extern __shared__ float sm[];
    float* Qu = sm + SQU;
    float* Qv = sm + SQV;
    float* Ks = sm + SKS;
    float* Vs = sm + SVS;
    float* Rs = sm + SRS;
    float* Sc = sm + SSC;
    float* Bs = sm + SBS;
    float* sM = sm + SMM;
    float* sL = sm + SLL;
    float* sC = sm + SCR;

    int tid = threadIdx.x;
    int warp = tid >> 5, lane = tid & 31;
    int g = lane >> 2, tg = lane & 3;
    int wm = (warp & 3) * 16;     // mma row base
    int wn = warp >> 2;           // col half (0/1)

    int bx = blockIdx.x;
    int head = blockIdx.y;
    int n = head >> 3, h = head & 7;

    const float* sq = seqs   + ((size_t)(n * Hh + h) * Ss) * DHh;
    const float* kq = keys   + ((size_t)(n * Hh + h) * Ss) * DHh;
    const float* vq = values + ((size_t)(n * Hh + h) * Ss) * DHh;
    const float* Rh = g_R + (size_t)h * (Pp * DHh);

    int lrow = tid >> 4;     // 0..15 row-loader base
    int lq4  = tid & 15;     // float4 slot

    float4 ub4 = *(const float4*)&u_bias[h * DHh + lq4 * 4];
    float4 vb4 = *(const float4*)&v_bias[h * DHh + lq4 * 4];

    const float scale = 0.125f;

    for (int ph = 0; ph < 2; ph++) {
        int qt = (ph == 0) ? (15 - bx) : bx;
        int i0 = qt * 64;

        __syncthreads();   // protect smem from previous half
        // Load Qu, Qv (row-major, tf32-rounded)
#pragma unroll
        for (int r = 0; r < 4; r++) {
            int row = lrow + r * 16;
            float4 s4 = *(const float4*)&sq[(size_t)(i0 + row) * DHh + lq4 * 4];
            Qu[row * 68 + lq4 * 4 + 0] = __uint_as_float(f2tf(s4.x + ub4.x));
            Qu[row * 68 + lq4 * 4 + 1] = __uint_as_float(f2tf(s4.y + ub4.y));
            Qu[row * 68 + lq4 * 4 + 2] = __uint_as_float(f2tf(s4.z + ub4.z));
            Qu[row * 68 + lq4 * 4 + 3] = __uint_as_float(f2tf(s4.w + ub4.w));
            Qv[row * 68 + lq4 * 4 + 0] = __uint_as_float(f2tf(s4.x + vb4.x));
            Qv[row * 68 + lq4 * 4 + 1] = __uint_as_float(f2tf(s4.y + vb4.y));
            Qv[row * 68 + lq4 * 4 + 2] = __uint_as_float(f2tf(s4.z + vb4.z));
            Qv[row * 68 + lq4 * 4 + 3] = __uint_as_float(f2tf(s4.w + vb4.w));
        }
        if (tid < 64) { sM[tid] = -INFINITY; sL[tid] = 0.0f; }

        float O[4][4];
#pragma unroll
        for (int a = 0; a < 4; a++)
#pragma unroll
            for (int b = 0; b < 4; b++) O[a][b] = 0.0f;

        for (int kt = 0; kt <= qt; kt++) {
            int j0 = kt * 64;
            int pbase = (Ss - 1) - i0 + j0 - 63;

            __syncthreads();   // prev iter consumers done
            // Load K, V (64 rows), R band (128 rows), tf32-rounded
#pragma unroll
            for (int r = 0; r < 4; r++) {
                int row = lrow + r * 16;
                float4 k4 = *(const float4*)&kq[(size_t)(j0 + row) * DHh + lq4 * 4];
                float4 v4 = *(const float4*)&vq[(size_t)(j0 + row) * DHh + lq4 * 4];
                Ks[row * 68 + lq4 * 4 + 0] = __uint_as_float(f2tf(k4.x));
                Ks[row * 68 + lq4 * 4 + 1] = __uint_as_float(f2tf(k4.y));
                Ks[row * 68 + lq4 * 4 + 2] = __uint_as_float(f2tf(k4.z));
                Ks[row * 68 + lq4 * 4 + 3] = __uint_as_float(f2tf(k4.w));
                Vs[row * 72 + lq4 * 4 + 0] = __uint_as_float(f2tf(v4.x));
                Vs[row * 72 + lq4 * 4 + 1] = __uint_as_float(f2tf(v4.y));
                Vs[row * 72 + lq4 * 4 + 2] = __uint_as_float(f2tf(v4.z));
                Vs[row * 72 + lq4 * 4 + 3] = __uint_as_float(f2tf(v4.w));
            }
#pragma unroll
            for (int r = 0; r < 8; r++) {
                int row = lrow + r * 16;
                float4 r4 = *(const float4*)&Rh[(size_t)(pbase + row) * DHh + lq4 * 4];
                Rs[row * 68 + lq4 * 4 + 0] = __uint_as_float(f2tf(r4.x));
                Rs[row * 68 + lq4 * 4 + 1] = __uint_as_float(f2tf(r4.y));
                Rs[row * 68 + lq4 * 4 + 2] = __uint_as_float(f2tf(r4.z));
                Rs[row * 68 + lq4 * 4 + 3] = __uint_as_float(f2tf(r4.w));
            }
            __syncthreads();

            // ---- AC = Qu @ K^T : warp -> rows wm..wm+15, cols wn*32..+31 ----
            float cS[4][4];
#pragma unroll
            for (int t = 0; t < 4; t++)
#pragma unroll
                for (int e = 0; e < 4; e++) cS[t][e] = 0.0f;
#pragma unroll
            for (int k0 = 0; k0 < 64; k0 += 8) {
                unsigned a0 = ldb(&Qu[(wm + g) * 68 + k0 + tg]);
                unsigned a1 = ldb(&Qu[(wm + g + 8) * 68 + k0 + tg]);
                unsigned a2 = ldb(&Qu[(wm + g) * 68 + k0 + tg + 4]);
                unsigned a3 = ldb(&Qu[(wm + g + 8) * 68 + k0 + tg + 4]);
#pragma unroll
                for (int nt = 0; nt < 4; nt++) {
                    int n0 = wn * 32 + nt * 8;
                    unsigned b0 = ldb(&Ks[(n0 + g) * 68 + k0 + tg]);
                    unsigned b1 = ldb(&Ks[(n0 + g) * 68 + k0 + tg + 4]);
                    mma_tf32(cS[nt], a0, a1, a2, a3, b0, b1);
                }
            }
#pragma unroll
            for (int nt = 0; nt < 4; nt++) {
                int n0 = wn * 32 + nt * 8;
                *(float2*)&Sc[(wm + g) * 68 + n0 + 2 * tg]     = make_float2(cS[nt][0], cS[nt][1]);
                *(float2*)&Sc[(wm + g + 8) * 68 + n0 + 2 * tg] = make_float2(cS[nt][2], cS[nt][3]);
            }

            // ---- BD = Qv @ Rband^T : warp -> rows wm..+15, cols wn*64..+63 ----
            float cB[8][4];
#pragma unroll
            for (int t = 0; t < 8; t++)
#pragma unroll
                for (int e = 0; e < 4; e++) cB[t][e] = 0.0f;
#pragma unroll
            for (int k0 = 0; k0 < 64; k0 += 8) {
                unsigned a0 = ldb(&Qv[(wm + g) * 68 + k0 + tg]);
                unsigned a1 = ldb(&Qv[(wm + g + 8) * 68 + k0 + tg]);
                unsigned a2 = ldb(&Qv[(wm + g) * 68 + k0 + tg + 4]);
                unsigned a3 = ldb(&Qv[(wm + g + 8) * 68 + k0 + tg + 4]);
#pragma unroll
                for (int nt = 0; nt < 8; nt++) {
                    int n0 = wn * 64 + nt * 8;
                    unsigned b0 = ldb(&Rs[(n0 + g) * 68 + k0 + tg]);
                    unsigned b1 = ldb(&Rs[(n0 + g) * 68 + k0 + tg + 4]);
                    mma_tf32(cB[nt], a0, a1, a2, a3, b0, b1);
                }
            }
#pragma unroll
            for (int nt = 0; nt < 8; nt++) {
                int n0 = wn * 64 + nt * 8;
                *(float2*)&Bs[(wm + g) * 132 + n0 + 2 * tg]     = make_float2(cB[nt][0], cB[nt][1]);
                *(float2*)&Bs[(wm + g + 8) * 132 + n0 + 2 * tg] = make_float2(cB[nt][2], cB[nt][3]);
            }
            __syncthreads();

            // ---- softmax: 4 threads/row, 16 cols each ----
            {
                int row = tid >> 2;
                int jg = tid & 3;
                float sv[16];
                float mx = -INFINITY;
#pragma unroll
                for (int q = 0; q < 4; q++) {
                    float4 a4 = *(const float4*)&Sc[row * 68 + jg * 16 + q * 4];
                    float av[4] = {a4.x, a4.y, a4.z, a4.w};
#pragma unroll
                    for (int c = 0; c < 4; c++) {
                        int j = jg * 16 + q * 4 + c;
                        float s = (av[c] + Bs[row * 132 + (j - row + 63)]) * scale;
                        if (kt == qt && j > row) s = -INFINITY;
                        sv[q * 4 + c] = s;
                        mx = fmaxf(mx, s);
                    }
                }
                mx = fmaxf(mx, __shfl_xor_sync(0xffffffffu, mx, 1));
                mx = fmaxf(mx, __shfl_xor_sync(0xffffffffu, mx, 2));
                float mold = sM[row];
                float mnew = fmaxf(mold, mx);
                float corr = __expf(mold - mnew);
                float sum = 0.0f;
#pragma unroll
                for (int c = 0; c < 16; c++) {
                    float e = __expf(sv[c] - mnew);
                    sum += e;
                    Sc[row * 68 + jg * 16 + c] = __uint_as_float(f2tf(e));
                }
                sum += __shfl_xor_sync(0xffffffffu, sum, 1);
                sum += __shfl_xor_sync(0xffffffffu, sum, 2);
                if (jg == 0) {
                    sM[row] = mnew;
                    sL[row] = sL[row] * corr + sum;
                    sC[row] = corr;
                }
            }
            __syncthreads();

            // ---- rescale O, then O += P @ V ----
            {
                float c0 = sC[wm + g];
                float c1 = sC[wm + g + 8];
#pragma unroll
                for (int nt = 0; nt < 4; nt++) {
                    O[nt][0] *= c0; O[nt][1] *= c0;
                    O[nt][2] *= c1; O[nt][3] *= c1;
                }
            }
#pragma unroll
            for (int k0 = 0; k0 < 64; k0 += 8) {
                unsigned a0 = ldb(&Sc[(wm + g) * 68 + k0 + tg]);
                unsigned a1 = ldb(&Sc[(wm + g + 8) * 68 + k0 + tg]);
                unsigned a2 = ldb(&Sc[(wm + g) * 68 + k0 + tg + 4]);
                unsigned a3 = ldb(&Sc[(wm + g + 8) * 68 + k0 + tg + 4]);
#pragma unroll
                for (int nt = 0; nt < 4; nt++) {
                    int n0 = wn * 32 + nt * 8;
                    unsigned b0 = ldb(&Vs[(k0 + tg) * 72 + n0 + g]);
                    unsigned b1 = ldb(&Vs[(k0 + tg + 4) * 72 + n0 + g]);
                    mma_tf32(O[nt], a0, a1, a2, a3, b0, b1);
                }
            }
        }

        // ---- epilogue ----
        float inv0 = 1.0f / sL[wm + g];
        float inv1 = 1.0f / sL[wm + g + 8];
        float* op = out + ((size_t)(n * Hh + h) * Ss + i0) * DHh;
#pragma unroll
        for (int nt = 0; nt < 4; nt++) {
            int n0 = wn * 32 + nt * 8;
            *(float2*)&op[(size_t)(wm + g) * DHh + n0 + 2 * tg] =
                make_float2(O[nt][0] * inv0, O[nt][1] * inv0);
            *(float2*)&op[(size_t)(wm + g + 8) * DHh + n0 + 2 * tg] =
                make_float2(O[nt][2] * inv1, O[nt][3] * inv1);
        }
    }
}

// ---------------------------------------------------------------------------
extern "C" void kernel_launch(void* const* d_in, const int* in_sizes, int n_in,
                              void* d_out, int out_size) {
    const float* seqs   = (const float*)d_in[0];
    const float* keys   = (const float*)d_in[1];
    const float* values = (const float*)d_in[2];
    const float* u_bias = (const float*)d_in[3];
    const float* v_bias = (const float*)d_in[4];
    const float* rproj  = (const float*)d_in[5];
    (void)in_sizes; (void)n_in; (void)out_size;

    const int smem_bytes = STOT * sizeof(float);  // ~154 KB
    static int configured = 0;
    cudaFuncSetAttribute(attn_kernel, cudaFuncAttributeMaxDynamicSharedMemorySize,
                         smem_bytes);
    (void)configured;

    enc_kernel<<<Pp, 256>>>();
    rproj_kernel<<<dim3(32, 8), 256>>>(rproj);
    attn_kernel<<<dim3(8, 16), 256, smem_bytes>>>(seqs, keys, values,
                                                  u_bias, v_bias,
                                                  (float*)d_out);
}